// round 7
// baseline (speedup 1.0000x reference)
#include <cuda_runtime.h>
#include <cstdint>

// Truncated path signature (Chen), trunc=4, B=128, S=512, D=8.
// One CTA/batch, 512 threads = 8 TIME CHUNKS x 64 threads.
// Chunk thread owns (i,j) and ALL k: 8 s3 + 64 s4 elems in packed f32x2 regs.
// FFMA2 is RF-bank-bound at rt=3/SMSP, so minimize packed instrs per element.
// 8 partial signatures staged simultaneously in 150KB smem; 3-level Chen tree.

#define BDIM 512
#define DSZ 8
#define TSTEPS 511
#define OUT_PER_B 4680   // 8 + 64 + 512 + 4096
#define SIG_F 4680       // floats per signature slot

typedef unsigned long long u64;

__device__ __forceinline__ u64 pack2(float x) {
    u64 r; uint32_t xi = __float_as_uint(x);
    asm("mov.b64 %0, {%1, %1};" : "=l"(r) : "r"(xi));
    return r;
}
__device__ __forceinline__ u64 f2mul(u64 a, u64 b) {
    u64 r; asm("mul.rn.f32x2 %0, %1, %2;" : "=l"(r) : "l"(a), "l"(b)); return r;
}
__device__ __forceinline__ u64 f2fma(u64 a, u64 b, u64 c) {
    u64 r; asm("fma.rn.f32x2 %0, %1, %2, %3;" : "=l"(r) : "l"(a), "l"(b), "l"(c)); return r;
}
__device__ __forceinline__ u64 f2add(u64 a, u64 b) {
    u64 r; asm("add.rn.f32x2 %0, %1, %2;" : "=l"(r) : "l"(a), "l"(b)); return r;
}
__device__ __forceinline__ float lo32(u64 a) { return __uint_as_float((uint32_t)a); }

struct Frag { float r4[8]; float r3, r2, r1; };

// Chen product C = A (x) B for output triple (i,j,k) = tid (tid < 512).
__device__ __forceinline__ void chen_comb(const float* __restrict__ A,
                                          const float* __restrict__ B,
                                          int tid, Frag& f) {
    const int ci = tid >> 6, cj = (tid >> 3) & 7, ck = tid & 7;
    const float a1 = A[ci];
    const float a2 = A[8 + ci * 8 + cj];
    const float a3 = A[72 + tid];

    const float4* B1p = reinterpret_cast<const float4*>(B);
    const float4* B2p = reinterpret_cast<const float4*>(B + 8 + ck * 8);
    const float4* B3p = reinterpret_cast<const float4*>(B + 72 + cj * 64 + ck * 8);
    const float4* A4p = reinterpret_cast<const float4*>(A + 584 + tid * 8);
    const float4* B4p = reinterpret_cast<const float4*>(B + 584 + tid * 8);

    float b1[8], b2[8], b3[8], a4[8], b4[8];
    *reinterpret_cast<float4*>(b1)     = B1p[0]; *reinterpret_cast<float4*>(b1 + 4) = B1p[1];
    *reinterpret_cast<float4*>(b2)     = B2p[0]; *reinterpret_cast<float4*>(b2 + 4) = B2p[1];
    *reinterpret_cast<float4*>(b3)     = B3p[0]; *reinterpret_cast<float4*>(b3 + 4) = B3p[1];
    *reinterpret_cast<float4*>(a4)     = A4p[0]; *reinterpret_cast<float4*>(a4 + 4) = A4p[1];
    *reinterpret_cast<float4*>(b4)     = B4p[0]; *reinterpret_cast<float4*>(b4 + 4) = B4p[1];

    #pragma unroll
    for (int l = 0; l < 8; ++l)
        f.r4[l] = a4[l] + b4[l] + a1 * b3[l] + a2 * b2[l] + a3 * b1[l];

    f.r3 = a3 + B[72 + tid] + a1 * B[8 + cj * 8 + ck] + a2 * B[ck];
    f.r2 = A[8 + tid] + B[8 + tid] + A[tid >> 3] * B[tid & 7];  // valid tid<64
    f.r1 = A[tid] + B[tid];                                      // valid tid<8
}

__device__ __forceinline__ void write_frag(float* __restrict__ S, int tid, const Frag& f) {
    float4* p = reinterpret_cast<float4*>(S + 584 + tid * 8);
    p[0] = make_float4(f.r4[0], f.r4[1], f.r4[2], f.r4[3]);
    p[1] = make_float4(f.r4[4], f.r4[5], f.r4[6], f.r4[7]);
    S[72 + tid] = f.r3;
    if (tid < 64) S[8 + tid] = f.r2;
    if (tid < 8)  S[tid] = f.r1;
}

// Dynamic smem: [0,16352) inc floats | [16384,49088) dupv u64
// Reused after main loop as 8 signature slots of 18720 B each = 149760 B total.
#define SMEM_BYTES 149760

__global__ __launch_bounds__(BDIM, 1)
void sig_kernel(const float* __restrict__ path, float* __restrict__ out) {
    extern __shared__ __align__(16) unsigned char smem_raw[];
    float* inc  = reinterpret_cast<float*>(smem_raw);
    u64*   dupv = reinterpret_cast<u64*>(smem_raw + 16384);
    float* sig  = reinterpret_cast<float*>(smem_raw);   // 8 slots of SIG_F floats

    const int b   = blockIdx.x;
    const int tid = threadIdx.x;
    const float* prow = path + (size_t)b * (512 * DSZ);

    for (int e = tid; e < TSTEPS * DSZ; e += BDIM) {
        float v = prow[e + DSZ] - prow[e];
        inc[e]  = v;
        dupv[e] = pack2(v);
    }
    __syncthreads();

    const int h  = tid >> 6;          // time chunk 0..7
    const int t6 = tid & 63;
    const int i  = t6 >> 3;           // 0..7
    const int j  = t6 & 7;            // 0..7

    u64 s1d = 0ull, s2d = 0ull;
    u64 s3d[8];
    u64 s4a[32];                      // [k*4 + lp], lp = l-pair
    #pragma unroll
    for (int z = 0; z < 8; ++z)  s3d[z] = 0ull;
    #pragma unroll
    for (int z = 0; z < 32; ++z) s4a[z] = 0ull;

    const u64 chalf = pack2(0.5f);
    const u64 c6    = pack2(0.16666666666666667f);
    const u64 c24   = pack2(0.041666666666666667f);

    const int t0 = h << 6;
    const int t1 = (h == 7) ? TSTEPS : (t0 + 64);

    for (int t = t0; t < t1; ++t) {
        const ulonglong2* incq = reinterpret_cast<const ulonglong2*>(inc + t * DSZ);
        ulonglong2 A  = incq[0];      // plain l-pairs (d0,d1),(d2,d3)
        ulonglong2 Bq = incq[1];      // (d4,d5),(d6,d7)
        const ulonglong2* kq = reinterpret_cast<const ulonglong2*>(dupv + t * DSZ);
        ulonglong2 K01 = kq[0];       // dup pairs k=0,1
        ulonglong2 K23 = kq[1];
        ulonglong2 K45 = kq[2];
        ulonglong2 K67 = kq[3];
        u64 did = dupv[t * DSZ + i];
        u64 djd = dupv[t * DSZ + j];

        // shared (i,j) chain — reads OLD s1,s2
        u64 bd = f2mul(did, djd);
        u64 gd = f2mul(djd, s1d);
        u64 ap = f2fma(chalf, s2d, f2fma(c6, gd, f2mul(c24, bd)));  // alpha
        u64 gp = f2fma(c6, bd, f2fma(chalf, gd, s2d));              // gamma

        u64 kk[8] = {K01.x, K01.y, K23.x, K23.y, K45.x, K45.y, K67.x, K67.y};
        #pragma unroll
        for (int k = 0; k < 8; ++k) {
            u64 ip = f2fma(kk[k], ap, s3d[k]);     // inner_k (dup)
            s3d[k] = f2fma(kk[k], gp, s3d[k]);
            s4a[k * 4 + 0] = f2fma(A.x,  ip, s4a[k * 4 + 0]);
            s4a[k * 4 + 1] = f2fma(A.y,  ip, s4a[k * 4 + 1]);
            s4a[k * 4 + 2] = f2fma(Bq.x, ip, s4a[k * 4 + 2]);
            s4a[k * 4 + 3] = f2fma(Bq.y, ip, s4a[k * 4 + 3]);
        }

        s2d = f2fma(djd, f2fma(chalf, did, s1d), s2d);
        s1d = f2add(s1d, did);
    }
    __syncthreads();   // inc/dupv dead; region becomes 8 sig slots

    // ---- stage this chunk's partial signature into slot h ----
    {
        float* slot = sig + h * SIG_F;
        if (j == 0) slot[i] = lo32(s1d);
        slot[8 + i * 8 + j] = lo32(s2d);
        const int base3 = i * 64 + j * 8;
        #pragma unroll
        for (int k = 0; k < 8; ++k) slot[72 + base3 + k] = lo32(s3d[k]);
        u64* p = reinterpret_cast<u64*>(slot + 584 + base3 * 8);
        #pragma unroll
        for (int z = 0; z < 32; ++z) p[z] = s4a[z];
    }
    __syncthreads();

    // ---- 3-level Chen tree; intermediate results live in registers ----
    Frag f01, f23, f45, f67;
    chen_comb(sig + 0 * SIG_F, sig + 1 * SIG_F, tid, f01);
    chen_comb(sig + 2 * SIG_F, sig + 3 * SIG_F, tid, f23);
    chen_comb(sig + 4 * SIG_F, sig + 5 * SIG_F, tid, f45);
    chen_comb(sig + 6 * SIG_F, sig + 7 * SIG_F, tid, f67);
    __syncthreads();

    write_frag(sig + 0 * SIG_F, tid, f01);
    write_frag(sig + 1 * SIG_F, tid, f23);
    write_frag(sig + 2 * SIG_F, tid, f45);
    write_frag(sig + 3 * SIG_F, tid, f67);
    __syncthreads();

    Frag g0, g1;
    chen_comb(sig + 0 * SIG_F, sig + 1 * SIG_F, tid, g0);
    chen_comb(sig + 2 * SIG_F, sig + 3 * SIG_F, tid, g1);
    __syncthreads();

    write_frag(sig + 0 * SIG_F, tid, g0);
    write_frag(sig + 1 * SIG_F, tid, g1);
    __syncthreads();

    Frag fF;
    chen_comb(sig + 0 * SIG_F, sig + 1 * SIG_F, tid, fF);
    write_frag(out + (size_t)b * OUT_PER_B, tid, fF);
}

extern "C" void kernel_launch(void* const* d_in, const int* in_sizes, int n_in,
                              void* d_out, int out_size) {
    const float* path = (const float*)d_in[0];
    float* out = (float*)d_out;
    cudaFuncSetAttribute(sig_kernel, cudaFuncAttributeMaxDynamicSharedMemorySize,
                         SMEM_BYTES);
    sig_kernel<<<128, BDIM, SMEM_BYTES>>>(path, out);
}

// round 16
// speedup vs baseline: 1.1089x; 1.1089x over previous
#include <cuda_runtime.h>
#include <cstdint>

// Truncated path signature (Chen), trunc=4, B=128, S=512, D=8.
// One CTA/batch, 384 threads = 6 TIME CHUNKS x 64 threads.
// Thread owns (i,j) and ALL k: 8 s3 + 64 s4 elems in packed f32x2 regs.
// BDIM=384 -> 170-reg ceiling: K=8 state fits WITHOUT spills (R6 lesson).
// K dup-pairs consumed immediately after load to minimize liveness.
// 6 partial signatures staged in smem; combined via Chen tree.

#define BDIM 384
#define DSZ 8
#define TSTEPS 511
#define OUT_PER_B 4680   // 8 + 64 + 512 + 4096
#define SIG_F 4680
#define NCHUNK 6
#define CHUNK_LEN 85     // 6*85 = 510; last chunk takes 86

typedef unsigned long long u64;

__device__ __forceinline__ u64 pack2(float x) {
    u64 r; uint32_t xi = __float_as_uint(x);
    asm("mov.b64 %0, {%1, %1};" : "=l"(r) : "r"(xi));
    return r;
}
__device__ __forceinline__ u64 f2mul(u64 a, u64 b) {
    u64 r; asm("mul.rn.f32x2 %0, %1, %2;" : "=l"(r) : "l"(a), "l"(b)); return r;
}
__device__ __forceinline__ u64 f2fma(u64 a, u64 b, u64 c) {
    u64 r; asm("fma.rn.f32x2 %0, %1, %2, %3;" : "=l"(r) : "l"(a), "l"(b), "l"(c)); return r;
}
__device__ __forceinline__ u64 f2add(u64 a, u64 b) {
    u64 r; asm("add.rn.f32x2 %0, %1, %2;" : "=l"(r) : "l"(a), "l"(b)); return r;
}
__device__ __forceinline__ float lo32(u64 a) { return __uint_as_float((uint32_t)a); }

struct Frag { float r4[8]; float r3, r2, r1; };

// Chen product C = A (x) B for output triple (i,j,k) = o (o < 512).
__device__ __forceinline__ void chen_comb(const float* __restrict__ A,
                                          const float* __restrict__ B,
                                          int o, Frag& f) {
    const int ci = o >> 6, cj = (o >> 3) & 7, ck = o & 7;
    const float a1 = A[ci];
    const float a2 = A[8 + ci * 8 + cj];
    const float a3 = A[72 + o];

    const float4* B1p = reinterpret_cast<const float4*>(B);
    const float4* B2p = reinterpret_cast<const float4*>(B + 8 + ck * 8);
    const float4* B3p = reinterpret_cast<const float4*>(B + 72 + cj * 64 + ck * 8);
    const float4* A4p = reinterpret_cast<const float4*>(A + 584 + o * 8);
    const float4* B4p = reinterpret_cast<const float4*>(B + 584 + o * 8);

    float b1[8], b2[8], b3[8], a4[8], b4[8];
    *reinterpret_cast<float4*>(b1)     = B1p[0]; *reinterpret_cast<float4*>(b1 + 4) = B1p[1];
    *reinterpret_cast<float4*>(b2)     = B2p[0]; *reinterpret_cast<float4*>(b2 + 4) = B2p[1];
    *reinterpret_cast<float4*>(b3)     = B3p[0]; *reinterpret_cast<float4*>(b3 + 4) = B3p[1];
    *reinterpret_cast<float4*>(a4)     = A4p[0]; *reinterpret_cast<float4*>(a4 + 4) = A4p[1];
    *reinterpret_cast<float4*>(b4)     = B4p[0]; *reinterpret_cast<float4*>(b4 + 4) = B4p[1];

    #pragma unroll
    for (int l = 0; l < 8; ++l)
        f.r4[l] = a4[l] + b4[l] + a1 * b3[l] + a2 * b2[l] + a3 * b1[l];

    f.r3 = a3 + B[72 + o] + a1 * B[8 + cj * 8 + ck] + a2 * B[ck];
    f.r2 = A[8 + o] + B[8 + o] + A[o >> 3] * B[o & 7];  // valid o<64
    f.r1 = A[o] + B[o];                                  // valid o<8
}

__device__ __forceinline__ void write_frag(float* __restrict__ S, int o, const Frag& f) {
    float4* p = reinterpret_cast<float4*>(S + 584 + o * 8);
    p[0] = make_float4(f.r4[0], f.r4[1], f.r4[2], f.r4[3]);
    p[1] = make_float4(f.r4[4], f.r4[5], f.r4[6], f.r4[7]);
    S[72 + o] = f.r3;
    if (o < 64) S[8 + o] = f.r2;
    if (o < 8)  S[o] = f.r1;
}

// Dynamic smem: [0,16352) inc floats | [16384,49088) dupv u64
// Reused after main loop as 6 signature slots of 18720 B = 112320 B total.
#define SMEM_BYTES 112320

__global__ __launch_bounds__(BDIM, 1)
void sig_kernel(const float* __restrict__ path, float* __restrict__ out) {
    extern __shared__ __align__(16) unsigned char smem_raw[];
    float* inc  = reinterpret_cast<float*>(smem_raw);
    u64*   dupv = reinterpret_cast<u64*>(smem_raw + 16384);
    float* sig  = reinterpret_cast<float*>(smem_raw);   // 6 slots of SIG_F floats

    const int b   = blockIdx.x;
    const int tid = threadIdx.x;
    const float* prow = path + (size_t)b * (512 * DSZ);

    for (int e = tid; e < TSTEPS * DSZ; e += BDIM) {
        float v = prow[e + DSZ] - prow[e];
        inc[e]  = v;
        dupv[e] = pack2(v);
    }
    __syncthreads();

    const int h  = tid >> 6;          // time chunk 0..5
    const int i  = (tid >> 3) & 7;    // 0..7
    const int j  = tid & 7;           // 0..7

    u64 s1d = 0ull, s2d = 0ull;
    u64 s3d[8];
    u64 s4a[32];                      // [k*4 + lpair]
    #pragma unroll
    for (int z = 0; z < 8; ++z)  s3d[z] = 0ull;
    #pragma unroll
    for (int z = 0; z < 32; ++z) s4a[z] = 0ull;

    const u64 chalf = pack2(0.5f);
    const u64 c6    = pack2(0.16666666666666667f);
    const u64 c24   = pack2(0.041666666666666667f);

    const int t0 = h * CHUNK_LEN;
    const int t1 = (h == NCHUNK - 1) ? TSTEPS : (t0 + CHUNK_LEN);

    for (int t = t0; t < t1; ++t) {
        const ulonglong2* incq = reinterpret_cast<const ulonglong2*>(inc + t * DSZ);
        ulonglong2 A  = incq[0];      // plain l-pairs (d0,d1),(d2,d3)
        ulonglong2 Bq = incq[1];      // (d4,d5),(d6,d7)
        u64 did = dupv[t * DSZ + i];
        u64 djd = dupv[t * DSZ + j];

        // chain on OLD s1,s2; retire did/djd/bd/gd before the k loop
        u64 bd = f2mul(did, djd);
        u64 gd = f2mul(djd, s1d);
        u64 ap = f2fma(chalf, s2d, f2fma(c6, gd, f2mul(c24, bd)));  // alpha
        u64 gp = f2fma(c6, bd, f2fma(chalf, gd, s2d));              // gamma
        s2d = f2fma(djd, f2fma(chalf, did, s1d), s2d);
        s1d = f2add(s1d, did);

        // k-loop: load one dup-pair at a time, consume immediately (liveness!)
        const ulonglong2* kq = reinterpret_cast<const ulonglong2*>(dupv + t * DSZ);
        #pragma unroll
        for (int kp = 0; kp < 4; ++kp) {
            ulonglong2 Kp = kq[kp];
            {
                u64 ip = f2fma(Kp.x, ap, s3d[2 * kp]);
                s3d[2 * kp] = f2fma(Kp.x, gp, s3d[2 * kp]);
                s4a[8 * kp + 0] = f2fma(A.x,  ip, s4a[8 * kp + 0]);
                s4a[8 * kp + 1] = f2fma(A.y,  ip, s4a[8 * kp + 1]);
                s4a[8 * kp + 2] = f2fma(Bq.x, ip, s4a[8 * kp + 2]);
                s4a[8 * kp + 3] = f2fma(Bq.y, ip, s4a[8 * kp + 3]);
            }
            {
                u64 ip = f2fma(Kp.y, ap, s3d[2 * kp + 1]);
                s3d[2 * kp + 1] = f2fma(Kp.y, gp, s3d[2 * kp + 1]);
                s4a[8 * kp + 4] = f2fma(A.x,  ip, s4a[8 * kp + 4]);
                s4a[8 * kp + 5] = f2fma(A.y,  ip, s4a[8 * kp + 5]);
                s4a[8 * kp + 6] = f2fma(Bq.x, ip, s4a[8 * kp + 6]);
                s4a[8 * kp + 7] = f2fma(Bq.y, ip, s4a[8 * kp + 7]);
            }
        }
    }
    __syncthreads();   // inc/dupv dead; region becomes 6 sig slots

    // ---- stage this chunk's partial signature into slot h ----
    {
        float* slot = sig + h * SIG_F;
        if (j == 0) slot[i] = lo32(s1d);
        slot[8 + i * 8 + j] = lo32(s2d);
        const int base3 = i * 64 + j * 8;
        #pragma unroll
        for (int k = 0; k < 8; ++k) slot[72 + base3 + k] = lo32(s3d[k]);
        u64* p = reinterpret_cast<u64*>(slot + 584 + base3 * 8);
        #pragma unroll
        for (int z = 0; z < 32; ++z) p[z] = s4a[z];
    }
    __syncthreads();

    // ---- Chen tree: P0=C0*C1, P1=C2*C3, P2=C4*C5; R=(P0*P1)*P2 ----
    // Each pass loops o = tid, tid+384 to cover 512 outputs.
    Frag f0[2], f1[2], f2[2];
    {
        int n = 0;
        for (int o = tid; o < 512; o += BDIM, ++n) {
            chen_comb(sig + 0 * SIG_F, sig + 1 * SIG_F, o, f0[n]);
            chen_comb(sig + 2 * SIG_F, sig + 3 * SIG_F, o, f1[n]);
            chen_comb(sig + 4 * SIG_F, sig + 5 * SIG_F, o, f2[n]);
        }
    }
    __syncthreads();
    {
        int n = 0;
        for (int o = tid; o < 512; o += BDIM, ++n) {
            write_frag(sig + 0 * SIG_F, o, f0[n]);
            write_frag(sig + 1 * SIG_F, o, f1[n]);
            write_frag(sig + 2 * SIG_F, o, f2[n]);
        }
    }
    __syncthreads();

    Frag g[2];
    {
        int n = 0;
        for (int o = tid; o < 512; o += BDIM, ++n)
            chen_comb(sig + 0 * SIG_F, sig + 1 * SIG_F, o, g[n]);
    }
    __syncthreads();
    {
        int n = 0;
        for (int o = tid; o < 512; o += BDIM, ++n)
            write_frag(sig + 3 * SIG_F, o, g[n]);
    }
    __syncthreads();

    {
        float* ob = out + (size_t)b * OUT_PER_B;
        for (int o = tid; o < 512; o += BDIM) {
            Frag ff;
            chen_comb(sig + 3 * SIG_F, sig + 2 * SIG_F, o, ff);
            write_frag(ob, o, ff);
        }
    }
}

extern "C" void kernel_launch(void* const* d_in, const int* in_sizes, int n_in,
                              void* d_out, int out_size) {
    const float* path = (const float*)d_in[0];
    float* out = (float*)d_out;
    cudaFuncSetAttribute(sig_kernel, cudaFuncAttributeMaxDynamicSharedMemorySize,
                         SMEM_BYTES);
    sig_kernel<<<128, BDIM, SMEM_BYTES>>>(path, out);
}